// round 3
// baseline (speedup 1.0000x reference)
#include <cuda_runtime.h>
#include <cuda_bf16.h>
#include <cmath>
#include <complex>

// ----------------------------------------------------------------------------
// Constants / layout
// ----------------------------------------------------------------------------
#define NF      196
#define STRIDE  197      // odd -> conflict-free column broadcasts
#define EPB     128
#define SMEM_BYTES (EPB * STRIDE * 4)

struct Params {
    float cg[1225];  // concatenated per-pair CG, layout (a*L2+b)*R + r
    float c5[45];    // sqrt(5) * wigner_3j(1,1,2), layout (m1*3+m2)*5 + M
};

// pair table: l1, l2, nch, feature offset, cg offset
// sizes: ss 9, sp 18, sd 15, ps 18, pp 36, pd 30, ds 15, dp 30, dd 25 = 196
// cg sizes (R^2): 1, 9, 25, 9, 81, 225, 25, 225, 625 = 1225

// ----------------------------------------------------------------------------
// Host-side CG computation: exact float64 mirror of the numpy reference.
// ----------------------------------------------------------------------------
typedef std::complex<double> cd;

static double hfact(int n) { double r = 1.0; for (int i = 2; i <= n; i++) r *= i; return r; }

static double su2_cg(int j1, int j2, int j3, int m1, int m2, int m3) {
    if (m3 != m1 + m2) return 0.0;
    int vmin = -j1 + j2 + m3;
    if (-j1 + m1 > vmin) vmin = -j1 + m1;
    if (0 > vmin) vmin = 0;
    int vmax = j2 + j3 + m1;
    if (j3 - j1 + j2 < vmax) vmax = j3 - j1 + j2;
    if (j3 + m3 < vmax) vmax = j3 + m3;
    double C = std::sqrt((2.0 * j3 + 1.0) * hfact(j3 + j1 - j2) * hfact(j3 - j1 + j2)
                         * hfact(j1 + j2 - j3) * hfact(j3 + m3) * hfact(j3 - m3)
                         / (hfact(j1 + j2 + j3 + 1) * hfact(j1 - m1) * hfact(j1 + m1)
                            * hfact(j2 - m2) * hfact(j2 + m2)));
    double S = 0.0;
    for (int v = vmin; v <= vmax; v++) {
        double sg = ((v + j2 + m2) & 1) ? -1.0 : 1.0;
        S += sg * hfact(j2 + j3 + m1 - v) * hfact(j1 - m1 + v)
             / (hfact(v) * hfact(j3 - j1 + j2 - v) * hfact(j3 + m3 - v)
                * hfact(v + j1 - j2 - m3));
    }
    return C * S;
}

static void change_basis(int l, cd* Q) {  // Q[(2l+1)^2], row-major Q[i*L+j]
    int L = 2 * l + 1;
    for (int i = 0; i < L * L; i++) Q[i] = cd(0, 0);
    double is2 = 1.0 / std::sqrt(2.0);
    for (int m = -l; m < 0; m++) {
        Q[(l + m) * L + (l - m)] = cd(is2, 0);
        Q[(l + m) * L + (l + m)] = cd(0, -is2);
    }
    Q[l * L + l] = cd(1, 0);
    for (int m = 1; m <= l; m++) {
        double sg = (m & 1) ? -1.0 : 1.0;
        Q[(l + m) * L + (l + m)] = cd(sg * is2, 0);
        Q[(l + m) * L + (l - m)] = cd(0, sg * is2);
    }
    cd ph(1, 0);
    const cd mi(0, -1);
    for (int k = 0; k < l; k++) ph *= mi;   // (-i)^l
    for (int i = 0; i < L * L; i++) Q[i] *= ph;
}

static void wigner3j(int l1, int l2, int l3, double* out) {  // out[L1*L2*L3]
    int L1 = 2 * l1 + 1, L2 = 2 * l2 + 1, L3 = 2 * l3 + 1;
    cd C[225];
    for (int i = 0; i < L1; i++)
        for (int k = 0; k < L2; k++)
            for (int n = 0; n < L3; n++)
                C[(i * L2 + k) * L3 + n] = cd(su2_cg(l1, l2, l3, i - l1, k - l2, n - l3), 0.0);
    cd Q1[25], Q2[25], Q3[81];
    change_basis(l1, Q1); change_basis(l2, Q2); change_basis(l3, Q3);
    double nrm = 0.0;
    for (int j = 0; j < L1; j++)
        for (int l = 0; l < L2; l++)
            for (int m = 0; m < L3; m++) {
                cd s(0, 0);
                for (int i = 0; i < L1; i++)
                    for (int k = 0; k < L2; k++)
                        for (int n = 0; n < L3; n++)
                            s += Q1[i * L1 + j] * Q2[k * L2 + l]
                               * std::conj(Q3[n * L3 + m]) * C[(i * L2 + k) * L3 + n];
                double v = s.real();
                out[(j * L2 + l) * L3 + m] = v;
                nrm += v * v;
            }
    nrm = std::sqrt(nrm);
    for (int t = 0; t < L1 * L2 * L3; t++) out[t] /= nrm;
}

static void build_params(Params& P) {
    static const int l1s[9]   = {0, 0, 0, 1, 1, 1, 2, 2, 2};
    static const int l2s[9]   = {0, 1, 2, 0, 1, 2, 0, 1, 2};
    static const int cgoff[9] = {0, 1, 10, 35, 44, 125, 350, 375, 600};
    for (int p = 0; p < 9; p++) {
        int l1 = l1s[p], l2 = l2s[p];
        int L1 = 2 * l1 + 1, L2 = 2 * l2 + 1, R = L1 * L2;
        double cg[625];
        int lmin = (l1 > l2) ? (l1 - l2) : (l2 - l1);
        int rof = 0;
        for (int l3 = lmin; l3 <= l1 + l2; l3++) {
            double w[225];
            wigner3j(l1, l2, l3, w);
            int L3 = 2 * l3 + 1;
            double sc = std::sqrt(2.0 * l3 + 1.0);
            for (int a = 0; a < L1; a++)
                for (int b = 0; b < L2; b++)
                    for (int nn = 0; nn < L3; nn++)
                        cg[(a * L2 + b) * R + rof + nn] = w[(a * L2 + b) * L3 + nn] * sc;
            rof += L3;
        }
        for (int t = 0; t < R * R; t++) P.cg[cgoff[p] + t] = (float)cg[t];
    }
    double w[45];
    wigner3j(1, 1, 2, w);
    double s5 = std::sqrt(5.0);
    for (int t = 0; t < 45; t++) P.c5[t] = (float)(w[t] * s5);
}

// ----------------------------------------------------------------------------
// Device
// ----------------------------------------------------------------------------
template <int L1, int L2, int NCH>
__device__ __forceinline__ void do_pair(float* __restrict__ row,
                                        const float* __restrict__ cg,
                                        const float* __restrict__ Dl,
                                        const float* __restrict__ Dr) {
    constexpr int R = L1 * L2;
    float rme[NCH * R];
#pragma unroll
    for (int i = 0; i < NCH * R; ++i) rme[i] = row[i];
#pragma unroll
    for (int q = 0; q < NCH; ++q) {
        // Hz[a][b] = sum_r CG[a][b][r] * rme[q][r]
        float Hz[R];
#pragma unroll
        for (int ab = 0; ab < R; ++ab) {
            float s = 0.f;
#pragma unroll
            for (int r = 0; r < R; ++r)
                s = fmaf(cg[ab * R + r], rme[q * R + r], s);
            Hz[ab] = s;
        }
        // T = Dl * Hz
        float T[R];
#pragma unroll
        for (int l = 0; l < L1; ++l)
#pragma unroll
            for (int b = 0; b < L2; ++b) {
                float s = 0.f;
#pragma unroll
                for (int m = 0; m < L1; ++m)
                    s = fmaf(Dl[l * L1 + m], Hz[m * L2 + b], s);
                T[l * L2 + b] = s;
            }
        // out[l][k] = sum_o T[l][o] * Dr[k][o]
#pragma unroll
        for (int l = 0; l < L1; ++l)
#pragma unroll
            for (int k = 0; k < L2; ++k) {
                float s = 0.f;
#pragma unroll
                for (int o = 0; o < L2; ++o)
                    s = fmaf(T[l * L2 + o], Dr[k * L2 + o], s);
                row[q * R + l * L2 + k] = s;
            }
    }
}

__global__ void __launch_bounds__(EPB, 2)
e3_kernel(const float* __restrict__ feat, const float* __restrict__ vec,
          float* __restrict__ out, int n, const __grid_constant__ Params P) {
    extern __shared__ float tile[];
    const int e0 = blockIdx.x * EPB;
    const int nvalid = min(EPB, n - e0);
    const int nf4 = nvalid * 49;   // 196 floats = 49 float4 per row

    // ---- coalesced load phase ----
    const float4* g4 = reinterpret_cast<const float4*>(feat + (size_t)e0 * NF);
    for (int i = threadIdx.x; i < nf4; i += EPB) {
        float4 v = g4[i];
        int r = i / 49;
        int c = (i - r * 49) * 4;
        float* p = &tile[r * STRIDE + c];
        p[0] = v.x; p[1] = v.y; p[2] = v.z; p[3] = v.w;
    }
    __syncthreads();

    // ---- compute phase: one thread = one edge, in place ----
    if (threadIdx.x < nvalid) {
        const int e = e0 + threadIdx.x;
        float vx = vec[3 * e + 0], vy = vec[3 * e + 1], vz = vec[3 * e + 2];
        float inv = rsqrtf(fmaf(vx, vx, fmaf(vy, vy, vz * vz)));
        vx *= inv; vy *= inv; vz *= inv;
        float cb = fminf(1.f, fmaxf(-1.f, vy));
        float sb = sqrtf(fmaxf(0.f, 1.f - cb * cb));
        float rho2 = fmaf(vx, vx, vz * vz);
        float ca, sa;
        if (rho2 > 0.f) {
            float ir = rsqrtf(rho2);
            ca = vz * ir; sa = vx * ir;
        } else { ca = 1.f; sa = 0.f; }

        // D1 = exp(alpha*G1) * exp(beta*G0), closed form (middle col = v_hat)
        float D1m[9] = {
            ca,   sa * sb,  sa * cb,
            0.f,  cb,      -sb,
            -sa,  ca * sb,  ca * cb
        };

        // D2 = C5^T (D1 (x) D1) C5, C5 = sqrt(5)*wigner_3j(1,1,2) (orthonormal cols)
        float D2m[25];
#pragma unroll
        for (int N = 0; N < 5; ++N) {
            float U[9];   // U[m2][n1] = sum_n2 D1[m2][n2] * C5[n1][n2][N]
#pragma unroll
            for (int m2 = 0; m2 < 3; ++m2)
#pragma unroll
                for (int n1 = 0; n1 < 3; ++n1) {
                    float s = 0.f;
#pragma unroll
                    for (int n2 = 0; n2 < 3; ++n2)
                        s = fmaf(D1m[m2 * 3 + n2], P.c5[(n1 * 3 + n2) * 5 + N], s);
                    U[m2 * 3 + n1] = s;
                }
            float E[9];   // E[m1][m2] = sum_n1 D1[m1][n1] * U[m2][n1]
#pragma unroll
            for (int m1 = 0; m1 < 3; ++m1)
#pragma unroll
                for (int m2 = 0; m2 < 3; ++m2) {
                    float s = 0.f;
#pragma unroll
                    for (int n1 = 0; n1 < 3; ++n1)
                        s = fmaf(D1m[m1 * 3 + n1], U[m2 * 3 + n1], s);
                    E[m1 * 3 + m2] = s;
                }
#pragma unroll
            for (int M = 0; M < 5; ++M) {
                float s = 0.f;
#pragma unroll
                for (int mm = 0; mm < 9; ++mm)
                    s = fmaf(P.c5[mm * 5 + M], E[mm], s);
                D2m[M * 5 + N] = s;
            }
        }

        float D0m[1] = {1.f};
        float* row = &tile[threadIdx.x * STRIDE];
        do_pair<1, 1, 9>(row + 0,   P.cg + 0,   D0m, D0m);  // s-s
        do_pair<1, 3, 6>(row + 9,   P.cg + 1,   D0m, D1m);  // s-p
        do_pair<1, 5, 3>(row + 27,  P.cg + 10,  D0m, D2m);  // s-d
        do_pair<3, 1, 6>(row + 42,  P.cg + 35,  D1m, D0m);  // p-s
        do_pair<3, 3, 4>(row + 60,  P.cg + 44,  D1m, D1m);  // p-p
        do_pair<3, 5, 2>(row + 96,  P.cg + 125, D1m, D2m);  // p-d
        do_pair<5, 1, 3>(row + 126, P.cg + 350, D2m, D0m);  // d-s
        do_pair<5, 3, 2>(row + 141, P.cg + 375, D2m, D1m);  // d-p
        do_pair<5, 5, 1>(row + 171, P.cg + 600, D2m, D2m);  // d-d
    }
    __syncthreads();

    // ---- coalesced store phase ----
    float4* o4 = reinterpret_cast<float4*>(out + (size_t)e0 * NF);
    for (int i = threadIdx.x; i < nf4; i += EPB) {
        int r = i / 49;
        int c = (i - r * 49) * 4;
        const float* p = &tile[r * STRIDE + c];
        o4[i] = make_float4(p[0], p[1], p[2], p[3]);
    }
}

// ----------------------------------------------------------------------------
// Launch
// ----------------------------------------------------------------------------
extern "C" void kernel_launch(void* const* d_in, const int* in_sizes, int n_in,
                              void* d_out, int out_size) {
    (void)n_in; (void)out_size;
    const float* feat = (const float*)d_in[0];
    const float* vec  = (const float*)d_in[1];
    float* out = (float*)d_out;
    const int n = in_sizes[0] / NF;

    Params P;
    build_params(P);

    cudaFuncSetAttribute(e3_kernel, cudaFuncAttributeMaxDynamicSharedMemorySize, SMEM_BYTES);
    int blocks = (n + EPB - 1) / EPB;
    e3_kernel<<<blocks, EPB, SMEM_BYTES>>>(feat, vec, out, n, P);
}